// round 1
// baseline (speedup 1.0000x reference)
#include <cuda_runtime.h>
#include <math.h>

#define NN    30000
#define NE    960000
#define ET    (NE + NN)
#define INDIM 4527
#define HOGD  4464
#define HID   128
#define NG    64

// ---------------- scratch (device globals; no dynamic alloc allowed) --------
__device__ float g_attn[NN * 2];          // softmax gate per node
__device__ float g_h1[NN * 256];          // GEMM1 output (2 heads x 128)
__device__ float g_as1[NN * 2];           // alpha_src layer1 (per head)
__device__ float g_ad1[NN * 2];           // alpha_dst layer1
__device__ float g_agg1[NN * 256];        // relu(agg + b1)  == input to GEMM2
__device__ float g_h2[NN * HID];          // GEMM2 output
__device__ float g_as2[NN];
__device__ float g_ad2[NN];
__device__ int   g_cntN[NN];              // per-dst degree counter
__device__ int   g_indptr[NN + 1];        // CSR row pointers (by dst)
__device__ int   g_cursor[NN];            // scatter cursors
__device__ int   g_srcs[ET];              // CSR src ids (self loop first)
__device__ float g_pool[NG * HID];        // graph pooling sums
__device__ int   g_gcnt[NG];              // graph node counts

// ---------------- helpers ---------------------------------------------------
__device__ __forceinline__ float warpSum(float v) {
#pragma unroll
    for (int o = 16; o; o >>= 1) v += __shfl_xor_sync(0xffffffffu, v, o);
    return v;
}
__device__ __forceinline__ float warpMax(float v) {
#pragma unroll
    for (int o = 16; o; o >>= 1) v = fmaxf(v, __shfl_xor_sync(0xffffffffu, v, o));
    return v;
}
__device__ __forceinline__ float lrelu(float v) { return v > 0.f ? v : 0.2f * v; }

// ---------------- init: reset counters / pooling buffers --------------------
__global__ void k_init() {
    int i = blockIdx.x * blockDim.x + threadIdx.x;
    if (i < NN) g_cntN[i] = 1;                 // self loop counts as 1
    if (i < NG * HID) g_pool[i] = 0.f;
    if (i < NG) g_gcnt[i] = 0;
}

// ---------------- attention gate: softmax(x @ attn_W + attn_b) --------------
__global__ void k_attn(const float* __restrict__ x,
                       const float* __restrict__ aW,
                       const float* __restrict__ ab) {
    int n = blockIdx.x;
    int t = threadIdx.x;  // 128 threads
    const float* xr = x + (size_t)n * INDIM;
    float p0 = 0.f, p1 = 0.f;
    for (int k = t; k < INDIM; k += 128) {
        float v = xr[k];
        p0 += v * aW[2 * k];
        p1 += v * aW[2 * k + 1];
    }
    p0 = warpSum(p0);
    p1 = warpSum(p1);
    __shared__ float s0[4], s1[4];
    if ((t & 31) == 0) { s0[t >> 5] = p0; s1[t >> 5] = p1; }
    __syncthreads();
    if (t == 0) {
        p0 = s0[0] + s0[1] + s0[2] + s0[3] + ab[0];
        p1 = s1[0] + s1[1] + s1[2] + s1[3] + ab[1];
        float m = fmaxf(p0, p1);
        float e0 = expf(p0 - m), e1 = expf(p1 - m);
        float inv = 1.f / (e0 + e1);
        g_attn[2 * n]     = e0 * inv;
        g_attn[2 * n + 1] = e1 * inv;
    }
}

// ---------------- GEMM1: h1 = (gate .* x) @ W1   (30000 x 4527 x 256) -------
// 128x128 tile, BK=16, 256 threads, 8x8 microtile. Gate applied on A load.
__global__ __launch_bounds__(256) void k_gemm1(const float* __restrict__ x,
                                               const float* __restrict__ W1) {
    __shared__ float As[16][132];   // padded row (132 floats = 528B, 16B aligned)
    __shared__ float Bs[16][128];
    const int bm = blockIdx.x * 128;
    const int bn = blockIdx.y * 128;
    const int tid = threadIdx.x;
    const int tx = tid & 15, ty = tid >> 4;
    const int ak = tid & 15, am = tid >> 4;
    const int bno = (tid & 31) * 4, bk = tid >> 5;

    // preload gate values for the 8 A-rows this thread loads
    float s0[8], s1[8];
#pragma unroll
    for (int r = 0; r < 8; r++) {
        int gm = bm + am + r * 16;
        if (gm < NN) { s0[r] = g_attn[2 * gm]; s1[r] = g_attn[2 * gm + 1]; }
        else         { s0[r] = 0.f; s1[r] = 0.f; }
    }

    float acc[8][8];
#pragma unroll
    for (int i = 0; i < 8; i++)
#pragma unroll
        for (int j = 0; j < 8; j++) acc[i][j] = 0.f;

    for (int k0 = 0; k0 < INDIM; k0 += 16) {
#pragma unroll
        for (int r = 0; r < 8; r++) {
            int m = am + r * 16;
            int gm = bm + m;
            int gk = k0 + ak;
            float v = 0.f;
            if (gm < NN && gk < INDIM)
                v = ((gk < HOGD) ? s0[r] : s1[r]) * x[(size_t)gm * INDIM + gk];
            As[ak][m] = v;
        }
#pragma unroll
        for (int r = 0; r < 2; r++) {
            int kk = bk + r * 8;
            int gk = k0 + kk;
            float4 v = make_float4(0.f, 0.f, 0.f, 0.f);
            if (gk < INDIM) v = *(const float4*)(W1 + (size_t)gk * 256 + bn + bno);
            *(float4*)&Bs[kk][bno] = v;
        }
        __syncthreads();
#pragma unroll
        for (int kk = 0; kk < 16; kk++) {
            float4 a0 = *(const float4*)&As[kk][ty * 8];
            float4 a1 = *(const float4*)&As[kk][ty * 8 + 4];
            float4 b0 = *(const float4*)&Bs[kk][tx * 8];
            float4 b1 = *(const float4*)&Bs[kk][tx * 8 + 4];
            float a[8] = {a0.x, a0.y, a0.z, a0.w, a1.x, a1.y, a1.z, a1.w};
            float b[8] = {b0.x, b0.y, b0.z, b0.w, b1.x, b1.y, b1.z, b1.w};
#pragma unroll
            for (int i = 0; i < 8; i++)
#pragma unroll
                for (int j = 0; j < 8; j++) acc[i][j] += a[i] * b[j];
        }
        __syncthreads();
    }
#pragma unroll
    for (int i = 0; i < 8; i++) {
        int gm = bm + ty * 8 + i;
        if (gm >= NN) continue;
        float* dst = g_h1 + (size_t)gm * 256 + bn + tx * 8;
        *(float4*)dst       = make_float4(acc[i][0], acc[i][1], acc[i][2], acc[i][3]);
        *(float4*)(dst + 4) = make_float4(acc[i][4], acc[i][5], acc[i][6], acc[i][7]);
    }
}

// ---------------- alpha_src / alpha_dst for layer 1 -------------------------
__global__ void k_alpha1(const float* __restrict__ as1,
                         const float* __restrict__ ad1) {
    int w = (blockIdx.x * blockDim.x + threadIdx.x) >> 5;
    int l = threadIdx.x & 31;
    if (w >= NN) return;
    const float* hr = g_h1 + (size_t)w * 256;
    float ps0 = 0, pd0 = 0, ps1 = 0, pd1 = 0;
#pragma unroll
    for (int i = 0; i < 4; i++) {
        int d = l + i * 32;
        float v0 = hr[d], v1 = hr[128 + d];
        ps0 += v0 * as1[d];        pd0 += v0 * ad1[d];
        ps1 += v1 * as1[128 + d];  pd1 += v1 * ad1[128 + d];
    }
    ps0 = warpSum(ps0); pd0 = warpSum(pd0);
    ps1 = warpSum(ps1); pd1 = warpSum(pd1);
    if (l == 0) {
        g_as1[2 * w] = ps0; g_as1[2 * w + 1] = ps1;
        g_ad1[2 * w] = pd0; g_ad1[2 * w + 1] = pd1;
    }
}

// ---------------- CSR build --------------------------------------------------
__global__ void k_count(const int* __restrict__ ei) {
    int e = blockIdx.x * blockDim.x + threadIdx.x;
    if (e < NE) atomicAdd(&g_cntN[ei[NE + e]], 1);
}

__global__ void k_scan() {  // single block, 1024 threads
    __shared__ int sh[1024];
    int t = threadIdx.x;
    const int CH = (NN + 1023) / 1024;  // 30
    int lo = t * CH, hi = min(lo + CH, NN);
    int s = 0;
    for (int i = lo; i < hi; i++) s += g_cntN[i];
    sh[t] = s;
    __syncthreads();
    for (int o = 1; o < 1024; o <<= 1) {
        int v = (t >= o) ? sh[t - o] : 0;
        __syncthreads();
        sh[t] += v;
        __syncthreads();
    }
    int run = (t == 0) ? 0 : sh[t - 1];
    for (int i = lo; i < hi; i++) { g_indptr[i] = run; run += g_cntN[i]; }
    if (t == 1023) g_indptr[NN] = sh[1023];
}

__global__ void k_self() {  // self-loop goes first in each bucket
    int i = blockIdx.x * blockDim.x + threadIdx.x;
    if (i < NN) { g_cursor[i] = 1; g_srcs[g_indptr[i]] = i; }
}

__global__ void k_scatter(const int* __restrict__ ei) {
    int e = blockIdx.x * blockDim.x + threadIdx.x;
    if (e < NE) {
        int s = ei[e], d = ei[NE + e];
        int pos = g_indptr[d] + atomicAdd(&g_cursor[d], 1);
        g_srcs[pos] = s;
    }
}

// ---------------- layer-1 aggregation: warp per dst node --------------------
__global__ void k_agg1(const float* __restrict__ b1) {
    int w = (blockIdx.x * blockDim.x + threadIdx.x) >> 5;
    int l = threadIdx.x & 31;
    if (w >= NN) return;
    int beg = g_indptr[w], end = g_indptr[w + 1];
    float ad0 = g_ad1[2 * w], ad1 = g_ad1[2 * w + 1];

    float m0 = -1e30f, m1 = -1e30f;
    for (int j = beg + l; j < end; j += 32) {
        int s = g_srcs[j];
        m0 = fmaxf(m0, lrelu(g_as1[2 * s] + ad0));
        m1 = fmaxf(m1, lrelu(g_as1[2 * s + 1] + ad1));
    }
    m0 = warpMax(m0); m1 = warpMax(m1);

    float d0 = 0.f, d1 = 0.f;
    for (int j = beg + l; j < end; j += 32) {
        int s = g_srcs[j];
        d0 += expf(lrelu(g_as1[2 * s] + ad0) - m0);
        d1 += expf(lrelu(g_as1[2 * s + 1] + ad1) - m1);
    }
    d0 = warpSum(d0); d1 = warpSum(d1);
    float i0 = 1.f / (d0 + 1e-16f), i1 = 1.f / (d1 + 1e-16f);

    float acc[8] = {0, 0, 0, 0, 0, 0, 0, 0};
    for (int base = beg; base < end; base += 32) {
        int j = base + l;
        int s = 0; float w0 = 0.f, w1 = 0.f;
        if (j < end) {
            s = g_srcs[j];
            w0 = expf(lrelu(g_as1[2 * s] + ad0) - m0) * i0;
            w1 = expf(lrelu(g_as1[2 * s + 1] + ad1) - m1) * i1;
        }
        int cnt = min(32, end - base);
        for (int q = 0; q < cnt; q++) {
            int   sq  = __shfl_sync(0xffffffffu, s, q);
            float w0q = __shfl_sync(0xffffffffu, w0, q);
            float w1q = __shfl_sync(0xffffffffu, w1, q);
            const float* hp = g_h1 + (size_t)sq * 256 + l;
            acc[0] += w0q * hp[0];   acc[1] += w0q * hp[32];
            acc[2] += w0q * hp[64];  acc[3] += w0q * hp[96];
            acc[4] += w1q * hp[128]; acc[5] += w1q * hp[160];
            acc[6] += w1q * hp[192]; acc[7] += w1q * hp[224];
        }
    }
#pragma unroll
    for (int i = 0; i < 8; i++) {
        int d = l + i * 32;
        float v = acc[i] + b1[d];
        g_agg1[(size_t)w * 256 + d] = v > 0.f ? v : 0.f;   // relu fused
    }
}

// ---------------- GEMM2: h2 = agg1 @ W2   (30000 x 256 x 128) ---------------
__global__ __launch_bounds__(256) void k_gemm2(const float* __restrict__ W2) {
    __shared__ float As[16][132];
    __shared__ float Bs[16][128];
    const int bm = blockIdx.x * 128;
    const int tid = threadIdx.x;
    const int tx = tid & 15, ty = tid >> 4;
    const int ak = tid & 15, am = tid >> 4;
    const int bno = (tid & 31) * 4, bk = tid >> 5;

    float acc[8][8];
#pragma unroll
    for (int i = 0; i < 8; i++)
#pragma unroll
        for (int j = 0; j < 8; j++) acc[i][j] = 0.f;

    for (int k0 = 0; k0 < 256; k0 += 16) {
#pragma unroll
        for (int r = 0; r < 8; r++) {
            int m = am + r * 16;
            int gm = bm + m;
            float v = 0.f;
            if (gm < NN) v = g_agg1[(size_t)gm * 256 + k0 + ak];
            As[ak][m] = v;
        }
#pragma unroll
        for (int r = 0; r < 2; r++) {
            int kk = bk + r * 8;
            float4 v = *(const float4*)(W2 + (size_t)(k0 + kk) * 128 + bno);
            *(float4*)&Bs[kk][bno] = v;
        }
        __syncthreads();
#pragma unroll
        for (int kk = 0; kk < 16; kk++) {
            float4 a0 = *(const float4*)&As[kk][ty * 8];
            float4 a1 = *(const float4*)&As[kk][ty * 8 + 4];
            float4 b0 = *(const float4*)&Bs[kk][tx * 8];
            float4 b1 = *(const float4*)&Bs[kk][tx * 8 + 4];
            float a[8] = {a0.x, a0.y, a0.z, a0.w, a1.x, a1.y, a1.z, a1.w};
            float b[8] = {b0.x, b0.y, b0.z, b0.w, b1.x, b1.y, b1.z, b1.w};
#pragma unroll
            for (int i = 0; i < 8; i++)
#pragma unroll
                for (int j = 0; j < 8; j++) acc[i][j] += a[i] * b[j];
        }
        __syncthreads();
    }
#pragma unroll
    for (int i = 0; i < 8; i++) {
        int gm = bm + ty * 8 + i;
        if (gm >= NN) continue;
        float* dst = g_h2 + (size_t)gm * 128 + tx * 8;
        *(float4*)dst       = make_float4(acc[i][0], acc[i][1], acc[i][2], acc[i][3]);
        *(float4*)(dst + 4) = make_float4(acc[i][4], acc[i][5], acc[i][6], acc[i][7]);
    }
}

// ---------------- alpha layer 2 ---------------------------------------------
__global__ void k_alpha2(const float* __restrict__ as2,
                         const float* __restrict__ ad2) {
    int w = (blockIdx.x * blockDim.x + threadIdx.x) >> 5;
    int l = threadIdx.x & 31;
    if (w >= NN) return;
    const float* hr = g_h2 + (size_t)w * 128;
    float ps = 0.f, pd = 0.f;
#pragma unroll
    for (int i = 0; i < 4; i++) {
        int d = l + i * 32;
        float v = hr[d];
        ps += v * as2[d];
        pd += v * ad2[d];
    }
    ps = warpSum(ps); pd = warpSum(pd);
    if (l == 0) { g_as2[w] = ps; g_ad2[w] = pd; }
}

// ---------------- layer-2 aggregation + fused pooling -----------------------
__global__ void k_agg2(const float* __restrict__ b2,
                       const int* __restrict__ batch) {
    int w = (blockIdx.x * blockDim.x + threadIdx.x) >> 5;
    int l = threadIdx.x & 31;
    if (w >= NN) return;
    int beg = g_indptr[w], end = g_indptr[w + 1];
    float ad = g_ad2[w];

    float m = -1e30f;
    for (int j = beg + l; j < end; j += 32)
        m = fmaxf(m, lrelu(g_as2[g_srcs[j]] + ad));
    m = warpMax(m);

    float den = 0.f;
    for (int j = beg + l; j < end; j += 32)
        den += expf(lrelu(g_as2[g_srcs[j]] + ad) - m);
    den = warpSum(den);
    float inv = 1.f / (den + 1e-16f);

    float acc[4] = {0, 0, 0, 0};
    for (int base = beg; base < end; base += 32) {
        int j = base + l;
        int s = 0; float ww = 0.f;
        if (j < end) {
            s = g_srcs[j];
            ww = expf(lrelu(g_as2[s] + ad) - m) * inv;
        }
        int cnt = min(32, end - base);
        for (int q = 0; q < cnt; q++) {
            int   sq = __shfl_sync(0xffffffffu, s, q);
            float wq = __shfl_sync(0xffffffffu, ww, q);
            const float* hp = g_h2 + (size_t)sq * 128 + l;
            acc[0] += wq * hp[0];  acc[1] += wq * hp[32];
            acc[2] += wq * hp[64]; acc[3] += wq * hp[96];
        }
    }
    int b = batch[w];
#pragma unroll
    for (int i = 0; i < 4; i++) {
        int d = l + i * 32;
        float v = acc[i] + b2[d];
        v = v > 0.f ? v : 0.f;
        atomicAdd(&g_pool[b * 128 + d], v);   // pooling fused (L2 atomics, tiny)
    }
    if (l == 0) atomicAdd(&g_gcnt[b], 1);
}

// ---------------- classifier head -------------------------------------------
__global__ void k_class(const float* __restrict__ Wc1, const float* __restrict__ bc1,
                        const float* __restrict__ Wc2, const float* __restrict__ bc2,
                        float* __restrict__ out) {
    int g = blockIdx.x, t = threadIdx.x;  // 128 threads
    __shared__ float p[128];
    __shared__ float z[64];
    float c = fmaxf((float)g_gcnt[g], 1.f);
    p[t] = g_pool[g * 128 + t] / c;
    __syncthreads();
    if (t < 64) {
        float s = bc1[t];
        for (int i = 0; i < 128; i++) s += p[i] * Wc1[i * 64 + t];
        z[t] = s > 0.f ? s : 0.f;
    }
    __syncthreads();
    if (t < 4) {
        float s = bc2[t];
        for (int i = 0; i < 64; i++) s += z[i] * Wc2[i * 4 + t];
        out[g * 4 + t] = s;
    }
}

// ---------------- launch -----------------------------------------------------
extern "C" void kernel_launch(void* const* d_in, const int* in_sizes, int n_in,
                              void* d_out, int out_size) {
    const float* x      = (const float*)d_in[0];
    const int*   ei     = (const int*)d_in[1];
    const int*   batch  = (const int*)d_in[2];
    const float* attn_W = (const float*)d_in[3];
    const float* attn_b = (const float*)d_in[4];
    const float* W1     = (const float*)d_in[5];
    const float* as1    = (const float*)d_in[6];
    const float* ad1    = (const float*)d_in[7];
    const float* b1     = (const float*)d_in[8];
    const float* W2     = (const float*)d_in[9];
    const float* as2    = (const float*)d_in[10];
    const float* ad2    = (const float*)d_in[11];
    const float* b2     = (const float*)d_in[12];
    const float* Wc1    = (const float*)d_in[13];
    const float* bc1    = (const float*)d_in[14];
    const float* Wc2    = (const float*)d_in[15];
    const float* bc2    = (const float*)d_in[16];
    float* out = (float*)d_out;

    k_init<<<(NN + 255) / 256, 256>>>();
    k_attn<<<NN, 128>>>(x, attn_W, attn_b);
    k_gemm1<<<dim3((NN + 127) / 128, 2), 256>>>(x, W1);
    k_alpha1<<<(NN * 32 + 255) / 256, 256>>>(as1, ad1);
    k_count<<<(NE + 255) / 256, 256>>>(ei);
    k_scan<<<1, 1024>>>();
    k_self<<<(NN + 255) / 256, 256>>>();
    k_scatter<<<(NE + 255) / 256, 256>>>(ei);
    k_agg1<<<(NN * 32 + 255) / 256, 256>>>(b1);
    k_gemm2<<<dim3((NN + 127) / 128, 1), 256>>>(W2);
    k_alpha2<<<(NN * 32 + 255) / 256, 256>>>(as2, ad2);
    k_agg2<<<(NN * 32 + 255) / 256, 256>>>(b2, batch);
    k_class<<<64, 128>>>(Wc1, bc1, Wc2, bc2, out);
}

// round 2
// speedup vs baseline: 2.6476x; 2.6476x over previous
#include <cuda_runtime.h>
#include <cuda_bf16.h>
#include <math.h>

#define NN    30000
#define NE    960000
#define ET    (NE + NN)
#define INDIM 4527
#define KPAD1 4544
#define HOGD  4464
#define HID   128
#define NG    64

// ---------------- scratch (device globals) ----------------------------------
__device__ float g_attn[NN * 2];
__device__ float g_h1[NN * 256];
__device__ float g_as1[NN * 2];
__device__ float g_ad1[NN * 2];
__device__ float g_agg1[NN * 256];
__device__ float g_h2[NN * HID];
__device__ float g_as2[NN];
__device__ float g_ad2[NN];
__device__ int   g_cntN[NN];
__device__ int   g_indptr[NN + 1];
__device__ int   g_cursor[NN];
__device__ int   g_srcs[ET];
__device__ float g_pool[NG * HID];
__device__ int   g_gcnt[NG];
// bf16 split weights, transposed to [n][k] with zero-padded k
__device__ __nv_bfloat16 g_W1Thi[256 * KPAD1];
__device__ __nv_bfloat16 g_W1Tlo[256 * KPAD1];
__device__ __nv_bfloat16 g_W2Thi[128 * 256];
__device__ __nv_bfloat16 g_W2Tlo[128 * 256];

// ---------------- helpers ---------------------------------------------------
__device__ __forceinline__ float warpSum(float v) {
#pragma unroll
    for (int o = 16; o; o >>= 1) v += __shfl_xor_sync(0xffffffffu, v, o);
    return v;
}
__device__ __forceinline__ float warpMax(float v) {
#pragma unroll
    for (int o = 16; o; o >>= 1) v = fmaxf(v, __shfl_xor_sync(0xffffffffu, v, o));
    return v;
}
__device__ __forceinline__ float lrelu(float v) { return v > 0.f ? v : 0.2f * v; }

__device__ __forceinline__ void mma16816(float c[4], const unsigned a[4],
                                         unsigned b0, unsigned b1) {
    asm volatile(
        "mma.sync.aligned.m16n8k16.row.col.f32.bf16.bf16.f32 "
        "{%0,%1,%2,%3}, {%4,%5,%6,%7}, {%8,%9}, {%0,%1,%2,%3};"
        : "+f"(c[0]), "+f"(c[1]), "+f"(c[2]), "+f"(c[3])
        : "r"(a[0]), "r"(a[1]), "r"(a[2]), "r"(a[3]), "r"(b0), "r"(b1));
}

// ---------------- init -------------------------------------------------------
__global__ void k_init() {
    int i = blockIdx.x * blockDim.x + threadIdx.x;
    if (i < NN) g_cntN[i] = 1;
    if (i < NG * HID) g_pool[i] = 0.f;
    if (i < NG) g_gcnt[i] = 0;
}

// ---------------- attention gate --------------------------------------------
__global__ void k_attn(const float* __restrict__ x,
                       const float* __restrict__ aW,
                       const float* __restrict__ ab) {
    int n = blockIdx.x;
    int t = threadIdx.x;  // 128
    const float* xr = x + (size_t)n * INDIM;
    float p0 = 0.f, p1 = 0.f;
    for (int k = t; k < INDIM; k += 128) {
        float v = xr[k];
        p0 += v * aW[2 * k];
        p1 += v * aW[2 * k + 1];
    }
    p0 = warpSum(p0);
    p1 = warpSum(p1);
    __shared__ float s0[4], s1[4];
    if ((t & 31) == 0) { s0[t >> 5] = p0; s1[t >> 5] = p1; }
    __syncthreads();
    if (t == 0) {
        p0 = s0[0] + s0[1] + s0[2] + s0[3] + ab[0];
        p1 = s1[0] + s1[1] + s1[2] + s1[3] + ab[1];
        float m = fmaxf(p0, p1);
        float e0 = expf(p0 - m), e1 = expf(p1 - m);
        float inv = 1.f / (e0 + e1);
        g_attn[2 * n]     = e0 * inv;
        g_attn[2 * n + 1] = e1 * inv;
    }
}

// ---------------- weight split (+transpose to [n][k]) -----------------------
__global__ void k_split(const float* __restrict__ W1, const float* __restrict__ W2) {
    int i = blockIdx.x * blockDim.x + threadIdx.x;
    if (i < 256 * KPAD1) {
        int n = i / KPAD1, k = i % KPAD1;
        float v = (k < INDIM) ? W1[(size_t)k * 256 + n] : 0.f;
        __nv_bfloat16 h = __float2bfloat16(v);
        g_W1Thi[i] = h;
        g_W1Tlo[i] = __float2bfloat16(v - __bfloat162float(h));
    }
    if (i < 128 * 256) {
        int n = i / 256, k = i % 256;
        float v = W2[k * 128 + n];
        __nv_bfloat16 h = __float2bfloat16(v);
        g_W2Thi[i] = h;
        g_W2Tlo[i] = __float2bfloat16(v - __bfloat162float(h));
    }
}

// ---------------- tensor-core GEMM: C[M,NTOT] = split(A') @ split(B)^T ------
// A' = (GATED ? gate.*A : A), fp32 -> bf16 hi/lo on the fly.
// BT: [NTOT][KPAD] bf16 hi/lo, zero-padded in k. C row stride = NTOT.
template <int K, int KPADT, int NTOT, bool GATED>
__global__ __launch_bounds__(256) void k_gemm(const float* __restrict__ A,
                                              const __nv_bfloat16* __restrict__ BThi,
                                              const __nv_bfloat16* __restrict__ BTlo,
                                              float* __restrict__ C) {
    constexpr int KT = (K + 31) / 32;
    __shared__ __nv_bfloat16 sA[2][128][40];  // [hi/lo][m][k]  (pad 40 -> conflict-free)
    __shared__ __nv_bfloat16 sB[2][128][40];  // [hi/lo][n][k]

    const int tid  = threadIdx.x;
    const int lane = tid & 31, warp = tid >> 5;
    const int wm = warp >> 2, wn = warp & 3;       // 2 x 4 warp grid (64x32 tiles)
    const int bn = blockIdx.x * 128;
    const int bm = blockIdx.y * 128;
    const int g  = lane >> 2, tq = lane & 3;

    float acc[4][4][4];
#pragma unroll
    for (int i = 0; i < 4; i++)
#pragma unroll
        for (int j = 0; j < 4; j++)
#pragma unroll
            for (int q = 0; q < 4; q++) acc[i][j][q] = 0.f;

    // gates for the 4 rows this thread loads
    const int arow = tid >> 3;       // 0..31
    const int acol = (tid & 7) * 4;  // 0..28
    float gA0[4], gA1[4];
#pragma unroll
    for (int p = 0; p < 4; p++) {
        int grow = bm + arow + p * 32;
        if (GATED && grow < NN) {
            gA0[p] = g_attn[2 * grow];
            gA1[p] = g_attn[2 * grow + 1];
        } else {
            gA0[p] = 1.f; gA1[p] = 1.f;
        }
    }

    float areg[16];
    uint4 breg[4];

    auto loadA = [&](int kt) {
        int k0 = kt * 32;
#pragma unroll
        for (int p = 0; p < 4; p++) {
            int grow = bm + arow + p * 32;
#pragma unroll
            for (int j = 0; j < 4; j++) {
                int gk = k0 + acol + j;
                float v = 0.f;
                if (grow < NN && gk < K) v = A[(size_t)grow * K + gk];
                if (GATED) v *= (gk < HOGD) ? gA0[p] : gA1[p];
                areg[p * 4 + j] = v;
            }
        }
    };
    auto loadB = [&](int kt) {
        int k0 = kt * 32;
        int row = tid >> 1;
        int c = (tid & 1) * 2;
        const uint4* ph = (const uint4*)&BThi[(size_t)(bn + row) * KPADT + k0];
        const uint4* pl = (const uint4*)&BTlo[(size_t)(bn + row) * KPADT + k0];
        breg[0] = ph[c]; breg[1] = ph[c + 1];
        breg[2] = pl[c]; breg[3] = pl[c + 1];
    };
    auto storeA = [&]() {
#pragma unroll
        for (int p = 0; p < 4; p++) {
            int row = arow + p * 32;
#pragma unroll
            for (int j = 0; j < 4; j += 2) {
                float v0 = areg[p * 4 + j], v1 = areg[p * 4 + j + 1];
                __nv_bfloat16 h0 = __float2bfloat16(v0);
                __nv_bfloat16 h1 = __float2bfloat16(v1);
                __nv_bfloat16 l0 = __float2bfloat16(v0 - __bfloat162float(h0));
                __nv_bfloat16 l1 = __float2bfloat16(v1 - __bfloat162float(h1));
                unsigned hp, lp;
                {
                    unsigned short u0 = *(unsigned short*)&h0, u1 = *(unsigned short*)&h1;
                    hp = (unsigned)u0 | ((unsigned)u1 << 16);
                    unsigned short w0 = *(unsigned short*)&l0, w1 = *(unsigned short*)&l1;
                    lp = (unsigned)w0 | ((unsigned)w1 << 16);
                }
                *(unsigned*)&sA[0][row][acol + j] = hp;
                *(unsigned*)&sA[1][row][acol + j] = lp;
            }
        }
    };
    auto storeB = [&]() {
        int row = tid >> 1;
        int base = (tid & 1) * 16;
        *(uint4*)&sB[0][row][base]     = breg[0];
        *(uint4*)&sB[0][row][base + 8] = breg[1];
        *(uint4*)&sB[1][row][base]     = breg[2];
        *(uint4*)&sB[1][row][base + 8] = breg[3];
    };
    auto mmaTile = [&]() {
#pragma unroll
        for (int ks = 0; ks < 2; ks++) {
            int k0 = ks * 16;
            int kc = k0 + 2 * tq;
            unsigned ah[4][4], al[4][4];
#pragma unroll
            for (int mt = 0; mt < 4; mt++) {
                int mr = wm * 64 + mt * 16 + g;
                ah[mt][0] = *(const unsigned*)&sA[0][mr][kc];
                ah[mt][1] = *(const unsigned*)&sA[0][mr + 8][kc];
                ah[mt][2] = *(const unsigned*)&sA[0][mr][kc + 8];
                ah[mt][3] = *(const unsigned*)&sA[0][mr + 8][kc + 8];
                al[mt][0] = *(const unsigned*)&sA[1][mr][kc];
                al[mt][1] = *(const unsigned*)&sA[1][mr + 8][kc];
                al[mt][2] = *(const unsigned*)&sA[1][mr][kc + 8];
                al[mt][3] = *(const unsigned*)&sA[1][mr + 8][kc + 8];
            }
#pragma unroll
            for (int nt = 0; nt < 4; nt++) {
                int nr = wn * 32 + nt * 8 + g;
                unsigned bh0 = *(const unsigned*)&sB[0][nr][kc];
                unsigned bh1 = *(const unsigned*)&sB[0][nr][kc + 8];
                unsigned bl0 = *(const unsigned*)&sB[1][nr][kc];
                unsigned bl1 = *(const unsigned*)&sB[1][nr][kc + 8];
#pragma unroll
                for (int mt = 0; mt < 4; mt++) {
                    mma16816(acc[mt][nt], ah[mt], bh0, bh1);
                    mma16816(acc[mt][nt], ah[mt], bl0, bl1);
                    mma16816(acc[mt][nt], al[mt], bh0, bh1);
                }
            }
        }
    };

    loadA(0); loadB(0);
    storeA(); storeB();
    __syncthreads();
    for (int kt = 0; kt < KT; kt++) {
        if (kt + 1 < KT) { loadA(kt + 1); loadB(kt + 1); }
        mmaTile();
        __syncthreads();
        if (kt + 1 < KT) {
            storeA(); storeB();
            __syncthreads();
        }
    }

    // epilogue
#pragma unroll
    for (int mt = 0; mt < 4; mt++) {
#pragma unroll
        for (int nt = 0; nt < 4; nt++) {
            int mr = bm + wm * 64 + mt * 16 + g;
            int nc = bn + wn * 32 + nt * 8 + 2 * tq;
            if (mr < NN) {
                float2 v0 = make_float2(acc[mt][nt][0], acc[mt][nt][1]);
                *(float2*)&C[(size_t)mr * NTOT + nc] = v0;
            }
            if (mr + 8 < NN) {
                float2 v1 = make_float2(acc[mt][nt][2], acc[mt][nt][3]);
                *(float2*)&C[(size_t)(mr + 8) * NTOT + nc] = v1;
            }
        }
    }
}

// ---------------- alpha layer 1 ---------------------------------------------
__global__ void k_alpha1(const float* __restrict__ as1,
                         const float* __restrict__ ad1) {
    int w = (blockIdx.x * blockDim.x + threadIdx.x) >> 5;
    int l = threadIdx.x & 31;
    if (w >= NN) return;
    const float* hr = g_h1 + (size_t)w * 256;
    float ps0 = 0, pd0 = 0, ps1 = 0, pd1 = 0;
#pragma unroll
    for (int i = 0; i < 4; i++) {
        int d = l + i * 32;
        float v0 = hr[d], v1 = hr[128 + d];
        ps0 += v0 * as1[d];        pd0 += v0 * ad1[d];
        ps1 += v1 * as1[128 + d];  pd1 += v1 * ad1[128 + d];
    }
    ps0 = warpSum(ps0); pd0 = warpSum(pd0);
    ps1 = warpSum(ps1); pd1 = warpSum(pd1);
    if (l == 0) {
        g_as1[2 * w] = ps0; g_as1[2 * w + 1] = ps1;
        g_ad1[2 * w] = pd0; g_ad1[2 * w + 1] = pd1;
    }
}

// ---------------- CSR build --------------------------------------------------
__global__ void k_count(const int* __restrict__ ei) {
    int e = blockIdx.x * blockDim.x + threadIdx.x;
    if (e < NE) atomicAdd(&g_cntN[ei[NE + e]], 1);
}

__global__ void k_scan() {
    __shared__ int sh[1024];
    int t = threadIdx.x;
    const int CH = (NN + 1023) / 1024;
    int lo = t * CH, hi = min(lo + CH, NN);
    int s = 0;
    for (int i = lo; i < hi; i++) s += g_cntN[i];
    sh[t] = s;
    __syncthreads();
    for (int o = 1; o < 1024; o <<= 1) {
        int v = (t >= o) ? sh[t - o] : 0;
        __syncthreads();
        sh[t] += v;
        __syncthreads();
    }
    int run = (t == 0) ? 0 : sh[t - 1];
    for (int i = lo; i < hi; i++) { g_indptr[i] = run; run += g_cntN[i]; }
    if (t == 1023) g_indptr[NN] = sh[1023];
}

__global__ void k_self() {
    int i = blockIdx.x * blockDim.x + threadIdx.x;
    if (i < NN) { g_cursor[i] = 1; g_srcs[g_indptr[i]] = i; }
}

__global__ void k_scatter(const int* __restrict__ ei) {
    int e = blockIdx.x * blockDim.x + threadIdx.x;
    if (e < NE) {
        int s = ei[e], d = ei[NE + e];
        int pos = g_indptr[d] + atomicAdd(&g_cursor[d], 1);
        g_srcs[pos] = s;
    }
}

// ---------------- layer-1 aggregation ---------------------------------------
__global__ void k_agg1(const float* __restrict__ b1) {
    int w = (blockIdx.x * blockDim.x + threadIdx.x) >> 5;
    int l = threadIdx.x & 31;
    if (w >= NN) return;
    int beg = g_indptr[w], end = g_indptr[w + 1];
    float ad0 = g_ad1[2 * w], ad1 = g_ad1[2 * w + 1];

    float m0 = -1e30f, m1 = -1e30f;
    for (int j = beg + l; j < end; j += 32) {
        int s = g_srcs[j];
        m0 = fmaxf(m0, lrelu(g_as1[2 * s] + ad0));
        m1 = fmaxf(m1, lrelu(g_as1[2 * s + 1] + ad1));
    }
    m0 = warpMax(m0); m1 = warpMax(m1);

    float d0 = 0.f, d1 = 0.f;
    for (int j = beg + l; j < end; j += 32) {
        int s = g_srcs[j];
        d0 += expf(lrelu(g_as1[2 * s] + ad0) - m0);
        d1 += expf(lrelu(g_as1[2 * s + 1] + ad1) - m1);
    }
    d0 = warpSum(d0); d1 = warpSum(d1);
    float i0 = 1.f / (d0 + 1e-16f), i1 = 1.f / (d1 + 1e-16f);

    float acc[8] = {0, 0, 0, 0, 0, 0, 0, 0};
    for (int base = beg; base < end; base += 32) {
        int j = base + l;
        int s = 0; float w0 = 0.f, w1 = 0.f;
        if (j < end) {
            s = g_srcs[j];
            w0 = expf(lrelu(g_as1[2 * s] + ad0) - m0) * i0;
            w1 = expf(lrelu(g_as1[2 * s + 1] + ad1) - m1) * i1;
        }
        int cnt = min(32, end - base);
        for (int q = 0; q < cnt; q++) {
            int   sq  = __shfl_sync(0xffffffffu, s, q);
            float w0q = __shfl_sync(0xffffffffu, w0, q);
            float w1q = __shfl_sync(0xffffffffu, w1, q);
            const float* hp = g_h1 + (size_t)sq * 256 + l;
            acc[0] += w0q * hp[0];   acc[1] += w0q * hp[32];
            acc[2] += w0q * hp[64];  acc[3] += w0q * hp[96];
            acc[4] += w1q * hp[128]; acc[5] += w1q * hp[160];
            acc[6] += w1q * hp[192]; acc[7] += w1q * hp[224];
        }
    }
#pragma unroll
    for (int i = 0; i < 8; i++) {
        int d = l + i * 32;
        float v = acc[i] + b1[d];
        g_agg1[(size_t)w * 256 + d] = v > 0.f ? v : 0.f;
    }
}

// ---------------- alpha layer 2 ---------------------------------------------
__global__ void k_alpha2(const float* __restrict__ as2,
                         const float* __restrict__ ad2) {
    int w = (blockIdx.x * blockDim.x + threadIdx.x) >> 5;
    int l = threadIdx.x & 31;
    if (w >= NN) return;
    const float* hr = g_h2 + (size_t)w * 128;
    float ps = 0.f, pd = 0.f;
#pragma unroll
    for (int i = 0; i < 4; i++) {
        int d = l + i * 32;
        float v = hr[d];
        ps += v * as2[d];
        pd += v * ad2[d];
    }
    ps = warpSum(ps); pd = warpSum(pd);
    if (l == 0) { g_as2[w] = ps; g_ad2[w] = pd; }
}

// ---------------- layer-2 aggregation + pooling ------------------------------
__global__ void k_agg2(const float* __restrict__ b2,
                       const int* __restrict__ batch) {
    int w = (blockIdx.x * blockDim.x + threadIdx.x) >> 5;
    int l = threadIdx.x & 31;
    if (w >= NN) return;
    int beg = g_indptr[w], end = g_indptr[w + 1];
    float ad = g_ad2[w];

    float m = -1e30f;
    for (int j = beg + l; j < end; j += 32)
        m = fmaxf(m, lrelu(g_as2[g_srcs[j]] + ad));
    m = warpMax(m);

    float den = 0.f;
    for (int j = beg + l; j < end; j += 32)
        den += expf(lrelu(g_as2[g_srcs[j]] + ad) - m);
    den = warpSum(den);
    float inv = 1.f / (den + 1e-16f);

    float acc[4] = {0, 0, 0, 0};
    for (int base = beg; base < end; base += 32) {
        int j = base + l;
        int s = 0; float ww = 0.f;
        if (j < end) {
            s = g_srcs[j];
            ww = expf(lrelu(g_as2[s] + ad) - m) * inv;
        }
        int cnt = min(32, end - base);
        for (int q = 0; q < cnt; q++) {
            int   sq = __shfl_sync(0xffffffffu, s, q);
            float wq = __shfl_sync(0xffffffffu, ww, q);
            const float* hp = g_h2 + (size_t)sq * 128 + l;
            acc[0] += wq * hp[0];  acc[1] += wq * hp[32];
            acc[2] += wq * hp[64]; acc[3] += wq * hp[96];
        }
    }
    int b = batch[w];
#pragma unroll
    for (int i = 0; i < 4; i++) {
        int d = l + i * 32;
        float v = acc[i] + b2[d];
        v = v > 0.f ? v : 0.f;
        atomicAdd(&g_pool[b * 128 + d], v);
    }
    if (l == 0) atomicAdd(&g_gcnt[b], 1);
}

// ---------------- classifier head -------------------------------------------
__global__ void k_class(const float* __restrict__ Wc1, const float* __restrict__ bc1,
                        const float* __restrict__ Wc2, const float* __restrict__ bc2,
                        float* __restrict__ out) {
    int g = blockIdx.x, t = threadIdx.x;
    __shared__ float p[128];
    __shared__ float z[64];
    float c = fmaxf((float)g_gcnt[g], 1.f);
    p[t] = g_pool[g * 128 + t] / c;
    __syncthreads();
    if (t < 64) {
        float s = bc1[t];
        for (int i = 0; i < 128; i++) s += p[i] * Wc1[i * 64 + t];
        z[t] = s > 0.f ? s : 0.f;
    }
    __syncthreads();
    if (t < 4) {
        float s = bc2[t];
        for (int i = 0; i < 64; i++) s += z[i] * Wc2[i * 4 + t];
        out[g * 4 + t] = s;
    }
}

// ---------------- launch -----------------------------------------------------
extern "C" void kernel_launch(void* const* d_in, const int* in_sizes, int n_in,
                              void* d_out, int out_size) {
    const float* x      = (const float*)d_in[0];
    const int*   ei     = (const int*)d_in[1];
    const int*   batch  = (const int*)d_in[2];
    const float* attn_W = (const float*)d_in[3];
    const float* attn_b = (const float*)d_in[4];
    const float* W1     = (const float*)d_in[5];
    const float* as1    = (const float*)d_in[6];
    const float* ad1    = (const float*)d_in[7];
    const float* b1     = (const float*)d_in[8];
    const float* W2     = (const float*)d_in[9];
    const float* as2    = (const float*)d_in[10];
    const float* ad2    = (const float*)d_in[11];
    const float* b2     = (const float*)d_in[12];
    const float* Wc1    = (const float*)d_in[13];
    const float* bc1    = (const float*)d_in[14];
    const float* Wc2    = (const float*)d_in[15];
    const float* bc2    = (const float*)d_in[16];
    float* out = (float*)d_out;

    float* p_h1;   cudaGetSymbolAddress((void**)&p_h1, g_h1);
    float* p_agg1; cudaGetSymbolAddress((void**)&p_agg1, g_agg1);
    float* p_h2;   cudaGetSymbolAddress((void**)&p_h2, g_h2);
    __nv_bfloat16 *p_w1h, *p_w1l, *p_w2h, *p_w2l;
    cudaGetSymbolAddress((void**)&p_w1h, g_W1Thi);
    cudaGetSymbolAddress((void**)&p_w1l, g_W1Tlo);
    cudaGetSymbolAddress((void**)&p_w2h, g_W2Thi);
    cudaGetSymbolAddress((void**)&p_w2l, g_W2Tlo);

    const int MB = (NN + 127) / 128;  // 235

    k_init<<<(NN + 255) / 256, 256>>>();
    k_attn<<<NN, 128>>>(x, attn_W, attn_b);
    k_split<<<(256 * KPAD1 + 255) / 256, 256>>>(W1, W2);
    k_gemm<INDIM, KPAD1, 256, true><<<dim3(2, MB), 256>>>(x, p_w1h, p_w1l, p_h1);
    k_alpha1<<<(NN * 32 + 255) / 256, 256>>>(as1, ad1);
    k_count<<<(NE + 255) / 256, 256>>>(ei);
    k_scan<<<1, 1024>>>();
    k_self<<<(NN + 255) / 256, 256>>>();
    k_scatter<<<(NE + 255) / 256, 256>>>(ei);
    k_agg1<<<(NN * 32 + 255) / 256, 256>>>(b1);
    k_gemm<256, 256, 128, false><<<dim3(1, MB), 256>>>(p_agg1, p_w2h, p_w2l, p_h2);
    k_alpha2<<<(NN * 32 + 255) / 256, 256>>>(as2, ad2);
    k_agg2<<<(NN * 32 + 255) / 256, 256>>>(b2, batch);
    k_class<<<64, 128>>>(Wc1, bc1, Wc2, bc2, out);
}